// round 9
// baseline (speedup 1.0000x reference)
#include <cuda_runtime.h>
#include <cuda_bf16.h>
#include <math.h>
#include <stdint.h>

// ---------------- problem constants ----------------
#define BATCH   128
#define C1      96
#define H1      72
#define P1      35
#define NPIX    1225
#define NPROTO  300
#define C2      192
#define P2      17
#define C3      384
#define P4      8
#define FDIM    4096
#define F5IN    12288
#define OUTD    128
#define ISPLIT  16

// ---------------- scratch ----------------
__device__ float g_conv1[128u*96*72*72];
__device__ float g_pool1[128u*96*1225];
__device__ float g_invn [128u*1225];
__device__ float g_featN[128u*1225*96];
__device__ float g_K    [128u*1225*300];
__device__ float g_u    [128u*1225];
__device__ float g_v    [128u*300];
__device__ float g_part [128u*ISPLIT*300];
__device__ float g_z    [128u*96*1225];
__device__ float g_c2   [128u*192*1225];
__device__ float g_p2   [128u*192*289];
__device__ float g_t1   [128u*384*289];
__device__ float g_t2   [128u*384*289];
__device__ float g_p4   [128u*192*64];
__device__ float g_f1   [128u*4096];
__device__ float g_f2   [128u*4096];
__device__ float g_f3   [128u*128];
__device__ float g_mean [4096];
__device__ float g_istd [4096];
__device__ float g_bnpart[1024];

static inline int cdiv(int a, int b) { return (a + b - 1) / b; }

// ---------------- bf16 split helpers ----------------
__device__ __forceinline__ void split_bf16(float v, uint32_t& hi, uint32_t& lo) {
    __nv_bfloat16 h = __float2bfloat16_rn(v);
    hi = (uint32_t)__bfloat16_as_ushort(h);
    float r = v - __bfloat162float(h);
    lo = (uint32_t)__bfloat16_as_ushort(__float2bfloat16_rn(r));
}

__device__ __forceinline__ void mma_bf16(float c[4], uint32_t a0, uint32_t a1,
                                         uint32_t a2, uint32_t a3,
                                         uint32_t b0, uint32_t b1) {
    asm volatile(
        "mma.sync.aligned.m16n8k16.row.col.f32.bf16.bf16.f32 "
        "{%0,%1,%2,%3}, {%4,%5,%6,%7}, {%8,%9}, {%0,%1,%2,%3};"
        : "+f"(c[0]), "+f"(c[1]), "+f"(c[2]), "+f"(c[3])
        : "r"(a0), "r"(a1), "r"(a2), "r"(a3), "r"(b0), "r"(b1));
}

// =====================================================================
// Implicit-GEMM 3x3 SAME conv, 3-product bf16 split (m16n8k16).
// 2 M-warp-groups x 4 N-groups; 32 couts/warp. Optional fused input
// BN+ReLU (bnM/bnI). Optional fused output BN stats (statsPart:
// sum at [co], sumsq at [512+co], accumulated via atomics).
// =====================================================================
template<int NTILES>
__global__ __launch_bounds__(256) void conv_bf16(
    const float* __restrict__ in, const float* __restrict__ w, float* __restrict__ out,
    int Cin, int H, int W, int Cout, int BH,
    const float* __restrict__ bnM, const float* __restrict__ bnI,
    float* __restrict__ statsPart)
{
    extern __shared__ uint32_t smem_u[];
    __shared__ float sstat[128];
    const int Wp = W + 2;
    int y0 = blockIdx.x * BH;
    int bandH = min(BH, H - y0);
    const int PS = (bandH + 2) * Wp;
    uint32_t* s_in_hi = smem_u;
    uint32_t* s_in_lo = s_in_hi + 8 * PS;
    uint32_t* s_w_hi  = s_in_lo + 8 * PS;
    uint32_t* s_w_lo  = s_w_hi + 64 * 73;

    int tid = threadIdx.x;
    if (tid < 128) sstat[tid] = 0.f;
    int wid = tid >> 5, lane = tid & 31;
    int warp_m = wid & 1, warp_n = wid >> 1;
    int b = blockIdx.z;
    int co0 = blockIdx.y * 64;
    int HW = H * W;
    int npix = bandH * W;

    int pixBase[NTILES];
#pragma unroll
    for (int j = 0; j < NTILES; j++) {
        int p = warp_n * (NTILES * 8) + j * 8 + (lane >> 2);
        if (p < npix) { int py = p / W, px = p - py * W; pixBase[j] = py * Wp + px; }
        else pixBase[j] = 0;
    }

    float acc[2][NTILES][4];
#pragma unroll
    for (int mt = 0; mt < 2; mt++)
#pragma unroll
        for (int j = 0; j < NTILES; j++)
#pragma unroll
            for (int e = 0; e < 4; e++) acc[mt][j][e] = 0.f;

    const float* inb = in + (size_t)b * Cin * HW;

    for (int ci0 = 0; ci0 < Cin; ci0 += 16) {
        for (int i = tid; i < 8 * PS; i += 256) {
            int pr = i / PS, rem = i - pr * PS;
            int r = rem / Wp, c = rem - r * Wp;
            int y = y0 - 1 + r, x = c - 1;
            float v0 = 0.f, v1 = 0.f;
            if (y >= 0 && y < H && x >= 0 && x < W) {
                const float* p = inb + (size_t)(ci0 + 2 * pr) * HW + y * W + x;
                v0 = __ldg(p); v1 = __ldg(p + HW);
                if (bnM) {
                    int c0 = ci0 + 2 * pr;
                    v0 = fmaxf((v0 - __ldg(&bnM[c0]))     * __ldg(&bnI[c0]),     0.f);
                    v1 = fmaxf((v1 - __ldg(&bnM[c0 + 1])) * __ldg(&bnI[c0 + 1]), 0.f);
                }
            }
            uint32_t h0, l0, h1, l1;
            split_bf16(v0, h0, l0);
            split_bf16(v1, h1, l1);
            s_in_hi[i] = h0 | (h1 << 16);
            s_in_lo[i] = l0 | (l1 << 16);
        }
        for (int i = tid; i < 64 * 72; i += 256) {
            int co = i / 72, rem = i - co * 72;
            int pr = rem / 9, tap = rem - pr * 9;
            const float* p = w + ((size_t)(co0 + co) * Cin + ci0 + 2 * pr) * 9 + tap;
            float v0 = __ldg(p), v1 = __ldg(p + 9);
            uint32_t h0, l0, h1, l1;
            split_bf16(v0, h0, l0);
            split_bf16(v1, h1, l1);
            s_w_hi[co * 73 + rem] = h0 | (h1 << 16);
            s_w_lo[co * 73 + rem] = l0 | (l1 << 16);
        }
        __syncthreads();

        int ar = lane >> 2, ac = lane & 3;
#pragma unroll
        for (int tap = 0; tap < 9; tap++) {
            int sh = (tap / 3) * Wp + (tap % 3);
            uint32_t ah[2][4], al[2][4];
#pragma unroll
            for (int mt = 0; mt < 2; mt++) {
                int woff = (warp_m * 32 + mt * 16 + ar) * 73 + ac * 9 + tap;
                ah[mt][0] = s_w_hi[woff];
                ah[mt][1] = s_w_hi[woff + 8 * 73];
                ah[mt][2] = s_w_hi[woff + 36];
                ah[mt][3] = s_w_hi[woff + 8 * 73 + 36];
                al[mt][0] = s_w_lo[woff];
                al[mt][1] = s_w_lo[woff + 8 * 73];
                al[mt][2] = s_w_lo[woff + 36];
                al[mt][3] = s_w_lo[woff + 8 * 73 + 36];
            }
            const uint32_t* bh0p = s_in_hi + ac * PS + sh;
            const uint32_t* bh1p = bh0p + 4 * PS;
            const uint32_t* bl0p = s_in_lo + ac * PS + sh;
            const uint32_t* bl1p = bl0p + 4 * PS;
#pragma unroll
            for (int j = 0; j < NTILES; j++) {
                uint32_t h0 = bh0p[pixBase[j]];
                uint32_t h1 = bh1p[pixBase[j]];
                uint32_t l0 = bl0p[pixBase[j]];
                uint32_t l1 = bl1p[pixBase[j]];
#pragma unroll
                for (int mt = 0; mt < 2; mt++) {
                    mma_bf16(acc[mt][j], ah[mt][0], ah[mt][1], ah[mt][2], ah[mt][3], h0, h1);
                    mma_bf16(acc[mt][j], ah[mt][0], ah[mt][1], ah[mt][2], ah[mt][3], l0, l1);
                    mma_bf16(acc[mt][j], al[mt][0], al[mt][1], al[mt][2], al[mt][3], h0, h1);
                }
            }
        }
        __syncthreads();
    }

    // epilogue (+ optional fused BN stats)
    int cr = lane >> 2, cc = lane & 3;
#pragma unroll
    for (int mt = 0; mt < 2; mt++) {
#pragma unroll
        for (int j = 0; j < NTILES; j++) {
#pragma unroll
            for (int e = 0; e < 4; e++) {
                int rr = cr + ((e >= 2) ? 8 : 0);
                int nn = 2 * cc + (e & 1);
                int p = warp_n * (NTILES * 8) + j * 8 + nn;
                if (p < npix) {
                    int py = y0 + p / W, px = p % W;
                    int lc = warp_m * 32 + mt * 16 + rr;
                    float v = acc[mt][j][e];
                    out[(((size_t)b * Cout + co0 + lc) * H + py) * W + px] = v;
                    if (statsPart) {
                        atomicAdd(&sstat[lc], v);
                        atomicAdd(&sstat[64 + lc], v * v);
                    }
                }
            }
        }
    }
    if (statsPart) {
        __syncthreads();
        if (tid < 128) {
            int c = tid >> 1, comp = tid & 1;
            atomicAdd(&statsPart[(comp ? 512 : 0) + co0 + c], sstat[comp * 64 + c]);
        }
    }
}

// ---------------- conv1 (Cin=2) — tiled FFMA kernel + fused stats ----------------
#define CT 16
__global__ __launch_bounds__(256) void conv3x3(
    const float* __restrict__ in, const float* __restrict__ w, float* __restrict__ out,
    int B, int Cin, int H, int W, int Cout, int tilesX, float* __restrict__ statsPart)
{
    __shared__ float s_in[18*18];
    __shared__ float s_w[CT*9];
    __shared__ float cstat[CT*2];
    int tile = blockIdx.x;
    int ty0 = (tile / tilesX) * 16, tx0 = (tile % tilesX) * 16;
    int co0 = blockIdx.y * CT;
    int b   = blockIdx.z;
    int tx = threadIdx.x, ty = threadIdx.y;
    int tid = ty * 16 + tx;
    if (tid < CT*2) cstat[tid] = 0.f;
    int ox = tx0 + tx, oy = ty0 + ty;
    bool valid = (ox < W) && (oy < H);
    float acc[CT];
#pragma unroll
    for (int i = 0; i < CT; i++) acc[i] = 0.f;

    const float* inb = in + (size_t)b * Cin * H * W;
    for (int ci = 0; ci < Cin; ci++) {
        const float* inc = inb + (size_t)ci * H * W;
        for (int i = tid; i < 18*18; i += 256) {
            int r = i / 18, c = i % 18;
            int y = ty0 - 1 + r, x = tx0 - 1 + c;
            s_in[i] = (y >= 0 && y < H && x >= 0 && x < W) ? inc[y * W + x] : 0.f;
        }
        if (tid < CT*9) {
            int co = tid / 9, k = tid % 9;
            s_w[tid] = w[((size_t)(co0 + co) * Cin + ci) * 9 + k];
        }
        __syncthreads();
        if (valid) {
            float r00 = s_in[(ty+0)*18 + tx+0], r01 = s_in[(ty+0)*18 + tx+1], r02 = s_in[(ty+0)*18 + tx+2];
            float r10 = s_in[(ty+1)*18 + tx+0], r11 = s_in[(ty+1)*18 + tx+1], r12 = s_in[(ty+1)*18 + tx+2];
            float r20 = s_in[(ty+2)*18 + tx+0], r21 = s_in[(ty+2)*18 + tx+1], r22 = s_in[(ty+2)*18 + tx+2];
#pragma unroll
            for (int co = 0; co < CT; co++) {
                const float* wp = &s_w[co*9];
                float a = r00*wp[0] + r01*wp[1] + r02*wp[2];
                a += r10*wp[3] + r11*wp[4] + r12*wp[5];
                a += r20*wp[6] + r21*wp[7] + r22*wp[8];
                acc[co] += a;
            }
        }
        __syncthreads();
    }
    if (valid) {
#pragma unroll
        for (int co = 0; co < CT; co++)
            out[(((size_t)b * Cout + co0 + co) * H + oy) * W + ox] = acc[co];
    }
    if (statsPart) {
        int lane = tid & 31;
#pragma unroll
        for (int co = 0; co < CT; co++) {
            float v = valid ? acc[co] : 0.f;
            float s1 = v, s2 = v * v;
#pragma unroll
            for (int o = 16; o > 0; o >>= 1) {
                s1 += __shfl_xor_sync(0xFFFFFFFFu, s1, o);
                s2 += __shfl_xor_sync(0xFFFFFFFFu, s2, o);
            }
            if (lane == 0) {
                atomicAdd(&cstat[co], s1);
                atomicAdd(&cstat[CT + co], s2);
            }
        }
        __syncthreads();
        if (tid < CT*2) {
            int c = tid >> 1, comp = tid & 1;
            atomicAdd(&statsPart[(comp ? 512 : 0) + co0 + c], cstat[comp * CT + c]);
        }
    }
}

// ---------------- BN stats finalize ----------------
__global__ void bn_stats_fin1(const float* __restrict__ bnp, float* __restrict__ mean,
                              float* __restrict__ istd, int C, float n)
{
    int c = blockIdx.x * blockDim.x + threadIdx.x;
    if (c >= C) return;
    float m = bnp[c] / n;
    mean[c] = m;
    istd[c] = rsqrtf(bnp[512 + c] / n - m * m + 1e-5f);
}

// ---------------- BN + ReLU + 3x3/2 maxpool fused ----------------
__global__ void bn_relu_pool(
    const float* __restrict__ x, const float* __restrict__ mean, const float* __restrict__ istd,
    float* __restrict__ out, int B, int C, int H, int W, int Ho, int Wo)
{
    int idx = blockIdx.x * blockDim.x + threadIdx.x;
    int total = B * C * Ho * Wo;
    if (idx >= total) return;
    int wo = idx % Wo; int t = idx / Wo;
    int ho = t % Ho;   t /= Ho;
    int c  = t % C;    int b = t / C;
    const float* xp = x + ((size_t)b * C + c) * H * W;
    float mx = -1e30f;
#pragma unroll
    for (int dy = 0; dy < 3; dy++)
#pragma unroll
        for (int dx = 0; dx < 3; dx++)
            mx = fmaxf(mx, xp[(2*ho + dy) * W + (2*wo + dx)]);
    float v = (mx - mean[c]) * istd[c];
    out[idx] = fmaxf(v, 0.f);
}

// ---------------- feature norms ----------------
__global__ __launch_bounds__(256) void feat_norms(
    const float* __restrict__ pool1, float* __restrict__ invn, int B, int C, int HW)
{
    int b = blockIdx.x;
    for (int n = threadIdx.x; n < HW; n += blockDim.x) {
        float s = 0.f;
        for (int c = 0; c < C; c++) {
            float v = pool1[((size_t)b * C + c) * HW + n];
            s += v * v;
        }
        invn[b * HW + n] = 1.f / fmaxf(sqrtf(s), 1e-12f);
    }
}

__global__ void feat_transpose(
    const float* __restrict__ pool1, const float* __restrict__ invn, float* __restrict__ featN,
    int B, int C, int HW)
{
    __shared__ float tile[32][33];
    int b = blockIdx.z;
    int n0 = blockIdx.x * 32, c0 = blockIdx.y * 32;
    for (int i = threadIdx.y; i < 32; i += 8) {
        int c = c0 + i, n = n0 + threadIdx.x;
        tile[i][threadIdx.x] = (c < C && n < HW) ? pool1[((size_t)b * C + c) * HW + n] : 0.f;
    }
    __syncthreads();
    for (int i = threadIdx.y; i < 32; i += 8) {
        int n = n0 + i, c = c0 + threadIdx.x;
        if (n < HW && c < C)
            featN[((size_t)b * HW + n) * C + c] = tile[threadIdx.x][i] * invn[b * HW + n];
    }
}

// ---------------- 128x128x8 register-blocked SGEMM NT (generic epilogue) ----
// epi: 0 none, 1 exp(10*(v-1)), 2 +bias. M % 128 == 0, K % 8 == 0.
__global__ __launch_bounds__(256) void sgemm128(
    const float* __restrict__ A, const float* __restrict__ Bm, float* __restrict__ C,
    int M, int N, int K, int epi, const float* __restrict__ bias)
{
    __shared__ float As[8][128];
    __shared__ float Bs[8][128];
    int m0 = blockIdx.y * 128, n0 = blockIdx.x * 128;
    int tid = threadIdx.x;
    int tx = tid & 15, ty = tid >> 4;
    float acc[8][8];
#pragma unroll
    for (int i = 0; i < 8; i++)
#pragma unroll
        for (int j = 0; j < 8; j++) acc[i][j] = 0.f;

    int lr = tid >> 1, lk = (tid & 1) * 4;
    for (int k0 = 0; k0 < K; k0 += 8) {
        float4 va = *(const float4*)&A[(size_t)(m0 + lr) * K + k0 + lk];
        float4 vb = make_float4(0.f, 0.f, 0.f, 0.f);
        if (n0 + lr < N) vb = *(const float4*)&Bm[(size_t)(n0 + lr) * K + k0 + lk];
        As[lk+0][lr] = va.x; As[lk+1][lr] = va.y; As[lk+2][lr] = va.z; As[lk+3][lr] = va.w;
        Bs[lk+0][lr] = vb.x; Bs[lk+1][lr] = vb.y; Bs[lk+2][lr] = vb.z; Bs[lk+3][lr] = vb.w;
        __syncthreads();
#pragma unroll
        for (int kk = 0; kk < 8; kk++) {
            float a[8], b[8];
            *(float4*)&a[0] = *(const float4*)&As[kk][ty*8];
            *(float4*)&a[4] = *(const float4*)&As[kk][ty*8+4];
            *(float4*)&b[0] = *(const float4*)&Bs[kk][tx*8];
            *(float4*)&b[4] = *(const float4*)&Bs[kk][tx*8+4];
#pragma unroll
            for (int i = 0; i < 8; i++)
#pragma unroll
                for (int j = 0; j < 8; j++) acc[i][j] += a[i] * b[j];
        }
        __syncthreads();
    }
#pragma unroll
    for (int i = 0; i < 8; i++) {
        int r = m0 + ty*8 + i;
#pragma unroll
        for (int j = 0; j < 8; j++) {
            int cn = n0 + tx*8 + j;
            if (cn < N) {
                float v = acc[i][j];
                if (epi == 1) v = __expf(10.f * (v - 1.f));
                else if (epi == 2) v += bias[cn];
                C[(size_t)r * N + cn] = v;
            }
        }
    }
}

// ---------------- SGEMM NT (small fc layers) ----------------
__global__ __launch_bounds__(256) void sgemm_nt(
    const float* __restrict__ A, const float* __restrict__ Bm, float* __restrict__ C,
    int M, int N, int K, int epi, const float* __restrict__ bias)
{
    const int BK = 16;
    __shared__ float As[BK][64];
    __shared__ float Bs[BK][64];
    int m0 = blockIdx.y * 64, n0 = blockIdx.x * 64;
    int tid = threadIdx.x;
    int tx = tid % 16, ty = tid / 16;
    float acc[4][4];
#pragma unroll
    for (int i = 0; i < 4; i++)
#pragma unroll
        for (int j = 0; j < 4; j++) acc[i][j] = 0.f;

    int lr = tid / 4, lk = (tid % 4) * 4;
    for (int k0 = 0; k0 < K; k0 += BK) {
        float4 va = make_float4(0.f, 0.f, 0.f, 0.f);
        float4 vb = make_float4(0.f, 0.f, 0.f, 0.f);
        int gm = m0 + lr, gn = n0 + lr;
        if (gm < M) va = *(const float4*)&A[(size_t)gm * K + k0 + lk];
        if (gn < N) vb = *(const float4*)&Bm[(size_t)gn * K + k0 + lk];
        As[lk+0][lr] = va.x; As[lk+1][lr] = va.y; As[lk+2][lr] = va.z; As[lk+3][lr] = va.w;
        Bs[lk+0][lr] = vb.x; Bs[lk+1][lr] = vb.y; Bs[lk+2][lr] = vb.z; Bs[lk+3][lr] = vb.w;
        __syncthreads();
#pragma unroll
        for (int kk = 0; kk < BK; kk++) {
            float a[4], b[4];
#pragma unroll
            for (int i = 0; i < 4; i++) a[i] = As[kk][ty*4 + i];
#pragma unroll
            for (int j = 0; j < 4; j++) b[j] = Bs[kk][tx*4 + j];
#pragma unroll
            for (int i = 0; i < 4; i++)
#pragma unroll
                for (int j = 0; j < 4; j++) acc[i][j] += a[i] * b[j];
        }
        __syncthreads();
    }
#pragma unroll
    for (int i = 0; i < 4; i++) {
        int r = m0 + ty*4 + i;
        if (r >= M) continue;
#pragma unroll
        for (int j = 0; j < 4; j++) {
            int cn = n0 + tx*4 + j;
            if (cn >= N) continue;
            float v = acc[i][j];
            if (epi == 1) v = __expf(10.f * (v - 1.f));
            else if (epi == 2) v += bias[cn];
            C[(size_t)r * N + cn] = v;
        }
    }
}

__global__ void fill_kernel(float* p, float v, int n) {
    int i = blockIdx.x * blockDim.x + threadIdx.x;
    if (i < n) p[i] = v;
}

// ---------------- Sinkhorn ----------------
__global__ __launch_bounds__(320) void sink_colsum(
    const float* __restrict__ K, const float* __restrict__ u, float* __restrict__ part,
    int n1, int n2)
{
    int b = blockIdx.x, sp = blockIdx.y;
    int j = threadIdx.x;
    if (j >= n2) return;
    int chunk = (n1 + ISPLIT - 1) / ISPLIT;
    int i0 = sp * chunk;
    int i1 = min(n1, i0 + chunk);
    const float* Kb = K + (size_t)b * n1 * n2;
    const float* ub = u + (size_t)b * n1;
    float s = 0.f;
    int i = i0;
    for (; i + 4 <= i1; i += 4) {
        float k0 = Kb[(size_t)(i+0) * n2 + j];
        float k1 = Kb[(size_t)(i+1) * n2 + j];
        float k2 = Kb[(size_t)(i+2) * n2 + j];
        float k3 = Kb[(size_t)(i+3) * n2 + j];
        s += k0 * ub[i+0] + k1 * ub[i+1] + k2 * ub[i+2] + k3 * ub[i+3];
    }
    for (; i < i1; i++) s += Kb[(size_t)i * n2 + j] * ub[i];
    part[((size_t)b * ISPLIT + sp) * n2 + j] = s;
}

__global__ __launch_bounds__(320) void sink_vupdate(
    const float* __restrict__ part, float* __restrict__ v, int n2, float bmarg)
{
    int b = blockIdx.x, j = threadIdx.x;
    if (j >= n2) return;
    float s = 0.f;
#pragma unroll
    for (int sp = 0; sp < ISPLIT; sp++) s += part[((size_t)b * ISPLIT + sp) * n2 + j];
    v[b * n2 + j] = bmarg / s;
}

// Fused: u_i = amarg / (K[i,:]·v)  AND  part[b,sp,j] = sum_i K[i,j]*u_i
// (one K pass per iteration instead of two).
__global__ __launch_bounds__(256) void sink_fused(
    const float* __restrict__ K, const float* __restrict__ v, float* __restrict__ u,
    float* __restrict__ part, int n1, int n2, float amarg, int doPart)
{
    __shared__ float sv[304];
    __shared__ float spart[304];
    int b = blockIdx.y, sp = blockIdx.x;
    int tid = threadIdx.x;
    for (int j = tid; j < n2; j += 256) sv[j] = v[b * n2 + j];
    if (doPart)
        for (int j = tid; j < 304; j += 256) spart[j] = 0.f;
    __syncthreads();
    int chunk = (n1 + ISPLIT - 1) / ISPLIT;
    int i0 = sp * chunk, i1 = min(n1, i0 + chunk);
    int wid = tid >> 5, lane = tid & 31;
    for (int i = i0 + wid; i < i1; i += 8) {
        const float* Kr = K + ((size_t)b * n1 + i) * n2;
        float kreg[10];
        float s = 0.f;
#pragma unroll
        for (int t = 0; t < 10; t++) {
            int j = lane + 32 * t;
            float kv = (j < n2) ? Kr[j] : 0.f;
            kreg[t] = kv;
            s += kv * ((j < n2) ? sv[j] : 0.f);
        }
#pragma unroll
        for (int o = 16; o > 0; o >>= 1) s += __shfl_xor_sync(0xFFFFFFFFu, s, o);
        float ui = amarg / s;
        if (lane == 0) u[b * n1 + i] = ui;
        if (doPart) {
#pragma unroll
            for (int t = 0; t < 10; t++) {
                int j = lane + 32 * t;
                if (j < n2) atomicAdd(&spart[j], kreg[t] * ui);
            }
        }
    }
    if (doPart) {
        __syncthreads();
        for (int j = tid; j < n2; j += 256)
            part[((size_t)b * ISPLIT + sp) * n2 + j] = spart[j];
    }
}

// ---------------- z GEMM ----------------
__global__ __launch_bounds__(256) void z_gemm(
    const float* __restrict__ Km, const float* __restrict__ u, const float* __restrict__ v,
    const float* __restrict__ P, float* __restrict__ z, float Bscale)
{
    __shared__ float As[8][128];
    __shared__ float Bs[8][96];
    __shared__ float sv[304];
    int b = blockIdx.y;
    int i0 = blockIdx.x * 128;
    int tid = threadIdx.x;
    for (int j = tid; j < 304; j += 256) sv[j] = (j < NPROTO) ? v[b * NPROTO + j] : 0.f;
    __syncthreads();
    int tx = tid & 15, ty = tid >> 4;
    float acc[8][6];
#pragma unroll
    for (int i = 0; i < 8; i++)
#pragma unroll
        for (int c = 0; c < 6; c++) acc[i][c] = 0.f;

    const float* Kb = Km + (size_t)b * NPIX * NPROTO;
    int li = tid >> 1, lk = (tid & 1) * 4;
    for (int k0 = 0; k0 < NPROTO; k0 += 8) {
        float4 va = make_float4(0.f, 0.f, 0.f, 0.f);
        if (i0 + li < NPIX && k0 + lk < NPROTO)
            va = *(const float4*)&Kb[(size_t)(i0 + li) * NPROTO + k0 + lk];
        As[lk+0][li] = va.x * sv[k0+lk+0];
        As[lk+1][li] = va.y * sv[k0+lk+1];
        As[lk+2][li] = va.z * sv[k0+lk+2];
        As[lk+3][li] = va.w * sv[k0+lk+3];
        for (int idx = tid; idx < 768; idx += 256) {
            int kk = idx / 96, c = idx - kk * 96;
            Bs[kk][c] = (k0 + kk < NPROTO) ? __ldg(&P[(k0 + kk) * 96 + c]) : 0.f;
        }
        __syncthreads();
#pragma unroll
        for (int kk = 0; kk < 8; kk++) {
            float a[8], bb[6];
            *(float4*)&a[0] = *(const float4*)&As[kk][ty*8];
            *(float4*)&a[4] = *(const float4*)&As[kk][ty*8+4];
            *(float2*)&bb[0] = *(const float2*)&Bs[kk][tx*6];
            *(float2*)&bb[2] = *(const float2*)&Bs[kk][tx*6+2];
            *(float2*)&bb[4] = *(const float2*)&Bs[kk][tx*6+4];
#pragma unroll
            for (int i = 0; i < 8; i++)
#pragma unroll
                for (int c = 0; c < 6; c++) acc[i][c] += a[i] * bb[c];
        }
        __syncthreads();
    }
#pragma unroll
    for (int ii = 0; ii < 8; ii++) {
        int i = i0 + ty * 8 + ii;
        if (i >= NPIX) continue;
        float s = Bscale * __ldg(&u[b * NPIX + i]);
#pragma unroll
        for (int cc = 0; cc < 6; cc++)
            z[((size_t)b * 96 + tx * 6 + cc) * NPIX + i] = acc[ii][cc] * s;
    }
}

// ---------------- BN1d ----------------
__global__ void bn1d_stats(const float* __restrict__ x, float* __restrict__ mean,
                           float* __restrict__ istd, int B, int F)
{
    int f = blockIdx.x * blockDim.x + threadIdx.x;
    if (f >= F) return;
    float s = 0.f, sq = 0.f;
    for (int b = 0; b < B; b++) {
        float v = x[(size_t)b * F + f];
        s += v; sq += v * v;
    }
    float m = s / B;
    mean[f] = m;
    istd[f] = rsqrtf(sq / B - m * m + 1e-5f);
}

__global__ void bn1d_apply_relu(float* __restrict__ x, const float* __restrict__ mean,
                                const float* __restrict__ istd, int total, int F)
{
    int i = blockIdx.x * blockDim.x + threadIdx.x;
    if (i >= total) return;
    int f = i % F;
    float v = (x[i] - mean[f]) * istd[f];
    x[i] = fmaxf(v, 0.f);
}

__global__ __launch_bounds__(128) void l2norm_rows(
    const float* __restrict__ x, float* __restrict__ out, int N)
{
    int r = blockIdx.x, t = threadIdx.x;
    float v = x[r * N + t];
    float s = v * v;
#pragma unroll
    for (int o = 16; o > 0; o >>= 1) s += __shfl_xor_sync(0xFFFFFFFFu, s, o);
    __shared__ float ws[4];
    if ((t & 31) == 0) ws[t >> 5] = s;
    __syncthreads();
    float tot = ws[0] + ws[1] + ws[2] + ws[3];
    out[r * N + t] = v / sqrtf(tot);
}

// ---------------- host orchestration ----------------
extern "C" void kernel_launch(void* const* d_in, const int* in_sizes, int n_in,
                              void* d_out, int out_size)
{
    const float* x      = (const float*)d_in[0];
    const float* sent_w = (const float*)d_in[1];
    const float* protos = (const float*)d_in[2];
    const float* w1     = (const float*)d_in[3];
    const float* w2     = (const float*)d_in[4];
    const float* w3     = (const float*)d_in[5];
    const float* w4     = (const float*)d_in[6];
    const float* w5     = (const float*)d_in[7];
    const float* w6     = (const float*)d_in[8];
    const float* w7     = (const float*)d_in[9];
    const float* b7     = (const float*)d_in[10];
    float* out = (float*)d_out;

    float *p_conv1, *p_pool1, *p_invn, *p_featN, *p_K, *p_u, *p_v, *p_part, *p_z;
    float *p_c2, *p_p2, *p_t1, *p_t2, *p_p4, *p_f1, *p_f2, *p_f3, *p_mean, *p_istd, *p_bnp;
    cudaGetSymbolAddress((void**)&p_conv1, g_conv1);
    cudaGetSymbolAddress((void**)&p_pool1, g_pool1);
    cudaGetSymbolAddress((void**)&p_invn,  g_invn);
    cudaGetSymbolAddress((void**)&p_featN, g_featN);
    cudaGetSymbolAddress((void**)&p_K,     g_K);
    cudaGetSymbolAddress((void**)&p_u,     g_u);
    cudaGetSymbolAddress((void**)&p_v,     g_v);
    cudaGetSymbolAddress((void**)&p_part,  g_part);
    cudaGetSymbolAddress((void**)&p_z,     g_z);
    cudaGetSymbolAddress((void**)&p_c2,    g_c2);
    cudaGetSymbolAddress((void**)&p_p2,    g_p2);
    cudaGetSymbolAddress((void**)&p_t1,    g_t1);
    cudaGetSymbolAddress((void**)&p_t2,    g_t2);
    cudaGetSymbolAddress((void**)&p_p4,    g_p4);
    cudaGetSymbolAddress((void**)&p_f1,    g_f1);
    cudaGetSymbolAddress((void**)&p_f2,    g_f2);
    cudaGetSymbolAddress((void**)&p_f3,    g_f3);
    cudaGetSymbolAddress((void**)&p_mean,  g_mean);
    cudaGetSymbolAddress((void**)&p_istd,  g_istd);
    cudaGetSymbolAddress((void**)&p_bnp,   g_bnpart);

    const int SM17 = (2 * 8 * (19 * 19) + 2 * 64 * 73) * 4;   // 60480 B
    const int SM35 = (2 * 8 * (11 * 37) + 2 * 64 * 73) * 4;   // 63424 B
    cudaFuncSetAttribute(conv_bf16<10>, cudaFuncAttributeMaxDynamicSharedMemorySize,
                         SM35 > SM17 ? SM35 : SM17);

    dim3 cb(16, 16);
    #define ZERO_BNP() fill_kernel<<<4, 256>>>(p_bnp, 0.f, 1024)

    // --- sentinel block: conv(2->96, 72x72) + fused stats + BN/ReLU/pool(72->35)
    {
        ZERO_BNP();
        int tilesX = cdiv(H1, 16);
        dim3 grid(tilesX * tilesX, C1 / CT, BATCH);
        conv3x3<<<grid, cb>>>(x, sent_w, p_conv1, BATCH, 2, H1, H1, C1, tilesX, p_bnp);
        bn_stats_fin1<<<cdiv(C1, 128), 128>>>(p_bnp, p_mean, p_istd, C1, (float)BATCH * H1 * H1);
        int total = BATCH * C1 * P1 * P1;
        bn_relu_pool<<<cdiv(total, 256), 256>>>(p_conv1, p_mean, p_istd, p_pool1,
                                                BATCH, C1, H1, H1, P1, P1);
    }

    // --- feature normalize + transpose
    feat_norms<<<BATCH, 256>>>(p_pool1, p_invn, BATCH, C1, NPIX);
    {
        dim3 grid(cdiv(NPIX, 32), cdiv(C1, 32), BATCH);
        feat_transpose<<<grid, dim3(32, 8)>>>(p_pool1, p_invn, p_featN, BATCH, C1, NPIX);
    }

    // --- S = featN @ protos^T, fused K = exp(10*(S-1))
    {
        dim3 grid(cdiv(NPROTO, 128), (BATCH * NPIX) / 128);
        sgemm128<<<grid, 256>>>(p_featN, protos, p_K, BATCH * NPIX, NPROTO, C1, 1, nullptr);
    }

    // --- Sinkhorn: init colsum (u=1), then 10 fused iterations (1 K-pass each)
    fill_kernel<<<cdiv(BATCH * NPIX, 256), 256>>>(p_u, 1.f, BATCH * NPIX);
    const float amarg = 1.f / (float)NPIX;
    const float bmarg = 1.f / (float)NPROTO;
    sink_colsum<<<dim3(BATCH, ISPLIT), 320>>>(p_K, p_u, p_part, NPIX, NPROTO);
    for (int it = 0; it < 10; it++) {
        sink_vupdate<<<BATCH, 320>>>(p_part, p_v, NPROTO, bmarg);
        sink_fused<<<dim3(ISPLIT, BATCH), 256>>>(p_K, p_v, p_u, p_part,
                                                 NPIX, NPROTO, amarg, it < 9);
    }

    // --- z = B * diag(u) K diag(v) protos
    z_gemm<<<dim3(cdiv(NPIX, 128), BATCH), 256>>>(p_K, p_u, p_v, protos, p_z, (float)BATCH);

    // --- block: conv(96->192, 35x35) + fused stats + BN/ReLU/pool(35->17)
    {
        ZERO_BNP();
        dim3 grid(4, C2 / 64, BATCH);
        conv_bf16<10><<<grid, 256, SM35>>>(p_z, w1, p_c2, C1, P1, P1, C2, 9,
                                           nullptr, nullptr, p_bnp);
        bn_stats_fin1<<<cdiv(C2, 128), 128>>>(p_bnp, p_mean, p_istd, C2, (float)BATCH * P1 * P1);
        int total = BATCH * C2 * P2 * P2;
        bn_relu_pool<<<cdiv(total, 256), 256>>>(p_c2, p_mean, p_istd, p_p2,
                                                BATCH, C2, P1, P1, P2, P2);
    }

    // --- block: conv(192->384, 17x17) -> t1 raw + fused stats
    {
        ZERO_BNP();
        dim3 grid(1, C3 / 64, BATCH);
        conv_bf16<10><<<grid, 256, SM17>>>(p_p2, w2, p_t1, C2, P2, P2, C3, 17,
                                           nullptr, nullptr, p_bnp);
        bn_stats_fin1<<<cdiv(C3, 128), 128>>>(p_bnp, p_mean, p_istd, C3, (float)BATCH * P2 * P2);
    }

    // --- block: conv(384->384, 17x17), input BN+ReLU fused -> t2 raw + fused stats
    {
        dim3 grid(1, C3 / 64, BATCH);
        ZERO_BNP();
        conv_bf16<10><<<grid, 256, SM17>>>(p_t1, w3, p_t2, C3, P2, P2, C3, 17,
                                           p_mean, p_istd, p_bnp);
        bn_stats_fin1<<<cdiv(C3, 128), 128>>>(p_bnp, p_mean, p_istd, C3, (float)BATCH * P2 * P2);
    }

    // --- block: conv(384->192, 17x17), input BN+ReLU fused -> t1 raw + stats, then pool
    {
        ZERO_BNP();
        dim3 grid(1, C2 / 64, BATCH);
        conv_bf16<10><<<grid, 256, SM17>>>(p_t2, w4, p_t1, C3, P2, P2, C2, 17,
                                           p_mean, p_istd, p_bnp);
        bn_stats_fin1<<<cdiv(C2, 128), 128>>>(p_bnp, p_mean, p_istd, C2, (float)BATCH * P2 * P2);
        int total = BATCH * C2 * P4 * P4;
        bn_relu_pool<<<cdiv(total, 256), 256>>>(p_t1, p_mean, p_istd, p_p4,
                                                BATCH, C2, P2, P2, P4, P4);
    }

    // --- fc5 (M=128 tile: w5 read once)
    {
        dim3 grid(cdiv(FDIM, 128), 1);
        sgemm128<<<grid, 256>>>(p_p4, w5, p_f1, BATCH, FDIM, F5IN, 0, nullptr);
        bn1d_stats<<<cdiv(FDIM, 256), 256>>>(p_f1, p_mean, p_istd, BATCH, FDIM);
        bn1d_apply_relu<<<cdiv(BATCH * FDIM, 256), 256>>>(p_f1, p_mean, p_istd, BATCH * FDIM, FDIM);
    }

    // --- fc6
    {
        dim3 grid(cdiv(FDIM, 128), 1);
        sgemm128<<<grid, 256>>>(p_f1, w6, p_f2, BATCH, FDIM, FDIM, 0, nullptr);
        bn1d_stats<<<cdiv(FDIM, 256), 256>>>(p_f2, p_mean, p_istd, BATCH, FDIM);
        bn1d_apply_relu<<<cdiv(BATCH * FDIM, 256), 256>>>(p_f2, p_mean, p_istd, BATCH * FDIM, FDIM);
    }

    // --- fc7 + L2 normalize
    {
        dim3 grid(cdiv(OUTD, 64), cdiv(BATCH, 64));
        sgemm_nt<<<grid, 256>>>(p_f2, w7, p_f3, BATCH, OUTD, FDIM, 2, b7);
        l2norm_rows<<<BATCH, 128>>>(p_f3, out, OUTD);
    }
}

// round 12
// speedup vs baseline: 1.3393x; 1.3393x over previous
#include <cuda_runtime.h>
#include <cuda_bf16.h>
#include <math.h>
#include <stdint.h>

// ---------------- problem constants ----------------
#define BATCH   128
#define C1      96
#define H1      72
#define P1      35
#define NPIX    1225
#define NPROTO  300
#define C2      192
#define P2      17
#define C3      384
#define P4      8
#define FDIM    4096
#define F5IN    12288
#define OUTD    128
#define ISPLIT  16
#define BNSPLIT 16

// ---------------- scratch ----------------
__device__ float g_conv1[128u*96*72*72];
__device__ float g_pool1[128u*96*1225];
__device__ float g_invn [128u*1225];
__device__ float g_featN[128u*1225*96];
__device__ float g_K    [128u*1225*300];
__device__ float g_u    [128u*1225];
__device__ float g_v    [128u*300];
__device__ float g_part [128u*ISPLIT*300];
__device__ float g_z    [128u*96*1225];
__device__ float g_c2   [128u*192*1225];
__device__ float g_p2   [128u*192*289];
__device__ float g_t1   [128u*384*289];
__device__ float g_t2   [128u*384*289];
__device__ float g_p4   [128u*192*64];
__device__ float g_f1   [128u*4096];
__device__ float g_f2   [128u*4096];
__device__ float g_f3   [128u*128];
__device__ float g_mean [4096];
__device__ float g_istd [4096];
__device__ float g_bnpart[384*BNSPLIT*2];

static inline int cdiv(int a, int b) { return (a + b - 1) / b; }

// ---------------- bf16 split helpers ----------------
__device__ __forceinline__ void split_bf16(float v, uint32_t& hi, uint32_t& lo) {
    __nv_bfloat16 h = __float2bfloat16_rn(v);
    hi = (uint32_t)__bfloat16_as_ushort(h);
    float r = v - __bfloat162float(h);
    lo = (uint32_t)__bfloat16_as_ushort(__float2bfloat16_rn(r));
}

__device__ __forceinline__ void mma_bf16(float c[4], uint32_t a0, uint32_t a1,
                                         uint32_t a2, uint32_t a3,
                                         uint32_t b0, uint32_t b1) {
    asm volatile(
        "mma.sync.aligned.m16n8k16.row.col.f32.bf16.bf16.f32 "
        "{%0,%1,%2,%3}, {%4,%5,%6,%7}, {%8,%9}, {%0,%1,%2,%3};"
        : "+f"(c[0]), "+f"(c[1]), "+f"(c[2]), "+f"(c[3])
        : "r"(a0), "r"(a1), "r"(a2), "r"(a3), "r"(b0), "r"(b1));
}

// =====================================================================
// Implicit-GEMM 3x3 SAME conv, 3-product bf16 split (m16n8k16).
// 2 M-warp-groups x 4 N-groups; 32 couts/warp. Optional fused input
// BN+ReLU (bnM/bnI, nullable).
// =====================================================================
template<int NTILES>
__global__ __launch_bounds__(256) void conv_bf16(
    const float* __restrict__ in, const float* __restrict__ w, float* __restrict__ out,
    int Cin, int H, int W, int Cout, int BH,
    const float* __restrict__ bnM, const float* __restrict__ bnI)
{
    extern __shared__ uint32_t smem_u[];
    const int Wp = W + 2;
    int y0 = blockIdx.x * BH;
    int bandH = min(BH, H - y0);
    const int PS = (bandH + 2) * Wp;
    uint32_t* s_in_hi = smem_u;
    uint32_t* s_in_lo = s_in_hi + 8 * PS;
    uint32_t* s_w_hi  = s_in_lo + 8 * PS;
    uint32_t* s_w_lo  = s_w_hi + 64 * 73;

    int tid = threadIdx.x;
    int wid = tid >> 5, lane = tid & 31;
    int warp_m = wid & 1, warp_n = wid >> 1;
    int b = blockIdx.z;
    int co0 = blockIdx.y * 64;
    int HW = H * W;
    int npix = bandH * W;

    int pixBase[NTILES];
#pragma unroll
    for (int j = 0; j < NTILES; j++) {
        int p = warp_n * (NTILES * 8) + j * 8 + (lane >> 2);
        if (p < npix) { int py = p / W, px = p - py * W; pixBase[j] = py * Wp + px; }
        else pixBase[j] = 0;
    }

    float acc[2][NTILES][4];
#pragma unroll
    for (int mt = 0; mt < 2; mt++)
#pragma unroll
        for (int j = 0; j < NTILES; j++)
#pragma unroll
            for (int e = 0; e < 4; e++) acc[mt][j][e] = 0.f;

    const float* inb = in + (size_t)b * Cin * HW;

    for (int ci0 = 0; ci0 < Cin; ci0 += 16) {
        for (int i = tid; i < 8 * PS; i += 256) {
            int pr = i / PS, rem = i - pr * PS;
            int r = rem / Wp, c = rem - r * Wp;
            int y = y0 - 1 + r, x = c - 1;
            float v0 = 0.f, v1 = 0.f;
            if (y >= 0 && y < H && x >= 0 && x < W) {
                const float* p = inb + (size_t)(ci0 + 2 * pr) * HW + y * W + x;
                v0 = __ldg(p); v1 = __ldg(p + HW);
                if (bnM) {
                    int c0 = ci0 + 2 * pr;
                    v0 = fmaxf((v0 - __ldg(&bnM[c0]))     * __ldg(&bnI[c0]),     0.f);
                    v1 = fmaxf((v1 - __ldg(&bnM[c0 + 1])) * __ldg(&bnI[c0 + 1]), 0.f);
                }
            }
            uint32_t h0, l0, h1, l1;
            split_bf16(v0, h0, l0);
            split_bf16(v1, h1, l1);
            s_in_hi[i] = h0 | (h1 << 16);
            s_in_lo[i] = l0 | (l1 << 16);
        }
        for (int i = tid; i < 64 * 72; i += 256) {
            int co = i / 72, rem = i - co * 72;
            int pr = rem / 9, tap = rem - pr * 9;
            const float* p = w + ((size_t)(co0 + co) * Cin + ci0 + 2 * pr) * 9 + tap;
            float v0 = __ldg(p), v1 = __ldg(p + 9);
            uint32_t h0, l0, h1, l1;
            split_bf16(v0, h0, l0);
            split_bf16(v1, h1, l1);
            s_w_hi[co * 73 + rem] = h0 | (h1 << 16);
            s_w_lo[co * 73 + rem] = l0 | (l1 << 16);
        }
        __syncthreads();

        int ar = lane >> 2, ac = lane & 3;
#pragma unroll
        for (int tap = 0; tap < 9; tap++) {
            int sh = (tap / 3) * Wp + (tap % 3);
            uint32_t ah[2][4], al[2][4];
#pragma unroll
            for (int mt = 0; mt < 2; mt++) {
                int woff = (warp_m * 32 + mt * 16 + ar) * 73 + ac * 9 + tap;
                ah[mt][0] = s_w_hi[woff];
                ah[mt][1] = s_w_hi[woff + 8 * 73];
                ah[mt][2] = s_w_hi[woff + 36];
                ah[mt][3] = s_w_hi[woff + 8 * 73 + 36];
                al[mt][0] = s_w_lo[woff];
                al[mt][1] = s_w_lo[woff + 8 * 73];
                al[mt][2] = s_w_lo[woff + 36];
                al[mt][3] = s_w_lo[woff + 8 * 73 + 36];
            }
            const uint32_t* bh0p = s_in_hi + ac * PS + sh;
            const uint32_t* bh1p = bh0p + 4 * PS;
            const uint32_t* bl0p = s_in_lo + ac * PS + sh;
            const uint32_t* bl1p = bl0p + 4 * PS;
#pragma unroll
            for (int j = 0; j < NTILES; j++) {
                uint32_t h0 = bh0p[pixBase[j]];
                uint32_t h1 = bh1p[pixBase[j]];
                uint32_t l0 = bl0p[pixBase[j]];
                uint32_t l1 = bl1p[pixBase[j]];
#pragma unroll
                for (int mt = 0; mt < 2; mt++) {
                    mma_bf16(acc[mt][j], ah[mt][0], ah[mt][1], ah[mt][2], ah[mt][3], h0, h1);
                    mma_bf16(acc[mt][j], ah[mt][0], ah[mt][1], ah[mt][2], ah[mt][3], l0, l1);
                    mma_bf16(acc[mt][j], al[mt][0], al[mt][1], al[mt][2], al[mt][3], h0, h1);
                }
            }
        }
        __syncthreads();
    }

    int cr = lane >> 2, cc = lane & 3;
#pragma unroll
    for (int mt = 0; mt < 2; mt++) {
#pragma unroll
        for (int j = 0; j < NTILES; j++) {
#pragma unroll
            for (int e = 0; e < 4; e++) {
                int rr = cr + ((e >= 2) ? 8 : 0);
                int nn = 2 * cc + (e & 1);
                int p = warp_n * (NTILES * 8) + j * 8 + nn;
                if (p < npix) {
                    int py = y0 + p / W, px = p % W;
                    int cout = co0 + warp_m * 32 + mt * 16 + rr;
                    out[(((size_t)b * Cout + cout) * H + py) * W + px] = acc[mt][j][e];
                }
            }
        }
    }
}

// ---------------- conv1 (Cin=2) — tiled FFMA kernel ----------------
#define CT 16
__global__ __launch_bounds__(256) void conv3x3(
    const float* __restrict__ in, const float* __restrict__ w, float* __restrict__ out,
    int B, int Cin, int H, int W, int Cout, int tilesX)
{
    __shared__ float s_in[18*18];
    __shared__ float s_w[CT*9];
    int tile = blockIdx.x;
    int ty0 = (tile / tilesX) * 16, tx0 = (tile % tilesX) * 16;
    int co0 = blockIdx.y * CT;
    int b   = blockIdx.z;
    int tx = threadIdx.x, ty = threadIdx.y;
    int tid = ty * 16 + tx;
    int ox = tx0 + tx, oy = ty0 + ty;
    bool valid = (ox < W) && (oy < H);
    float acc[CT];
#pragma unroll
    for (int i = 0; i < CT; i++) acc[i] = 0.f;

    const float* inb = in + (size_t)b * Cin * H * W;
    for (int ci = 0; ci < Cin; ci++) {
        const float* inc = inb + (size_t)ci * H * W;
        for (int i = tid; i < 18*18; i += 256) {
            int r = i / 18, c = i % 18;
            int y = ty0 - 1 + r, x = tx0 - 1 + c;
            s_in[i] = (y >= 0 && y < H && x >= 0 && x < W) ? inc[y * W + x] : 0.f;
        }
        if (tid < CT*9) {
            int co = tid / 9, k = tid % 9;
            s_w[tid] = w[((size_t)(co0 + co) * Cin + ci) * 9 + k];
        }
        __syncthreads();
        if (valid) {
            float r00 = s_in[(ty+0)*18 + tx+0], r01 = s_in[(ty+0)*18 + tx+1], r02 = s_in[(ty+0)*18 + tx+2];
            float r10 = s_in[(ty+1)*18 + tx+0], r11 = s_in[(ty+1)*18 + tx+1], r12 = s_in[(ty+1)*18 + tx+2];
            float r20 = s_in[(ty+2)*18 + tx+0], r21 = s_in[(ty+2)*18 + tx+1], r22 = s_in[(ty+2)*18 + tx+2];
#pragma unroll
            for (int co = 0; co < CT; co++) {
                const float* wp = &s_w[co*9];
                float a = r00*wp[0] + r01*wp[1] + r02*wp[2];
                a += r10*wp[3] + r11*wp[4] + r12*wp[5];
                a += r20*wp[6] + r21*wp[7] + r22*wp[8];
                acc[co] += a;
            }
        }
        __syncthreads();
    }
    if (valid) {
#pragma unroll
        for (int co = 0; co < CT; co++)
            out[(((size_t)b * Cout + co0 + co) * H + oy) * W + ox] = acc[co];
    }
}

// ---------------- BN2d stats: batch-split partials + finalize ----------------
__global__ __launch_bounds__(256) void bn2d_stats_part(
    const float* __restrict__ x, float* __restrict__ part, int B, int C, int HW)
{
    int c = blockIdx.x, sp = blockIdx.y;
    float s = 0.f, sq = 0.f;
    for (int b = sp; b < B; b += BNSPLIT) {
        const float* xp = x + ((size_t)b * C + c) * HW;
        for (int p = threadIdx.x; p < HW; p += blockDim.x) {
            float v = xp[p];
            s += v; sq += v * v;
        }
    }
    __shared__ float rs[256], rq[256];
    rs[threadIdx.x] = s; rq[threadIdx.x] = sq;
    __syncthreads();
    for (int o = 128; o > 0; o >>= 1) {
        if (threadIdx.x < o) { rs[threadIdx.x] += rs[threadIdx.x + o]; rq[threadIdx.x] += rq[threadIdx.x + o]; }
        __syncthreads();
    }
    if (threadIdx.x == 0) {
        part[(c * BNSPLIT + sp) * 2 + 0] = rs[0];
        part[(c * BNSPLIT + sp) * 2 + 1] = rq[0];
    }
}

__global__ void bn2d_stats_fin(const float* __restrict__ part, float* __restrict__ mean,
                               float* __restrict__ istd, int C, float n)
{
    int c = blockIdx.x * blockDim.x + threadIdx.x;
    if (c >= C) return;
    float s = 0.f, sq = 0.f;
#pragma unroll
    for (int sp = 0; sp < BNSPLIT; sp++) {
        s  += part[(c * BNSPLIT + sp) * 2 + 0];
        sq += part[(c * BNSPLIT + sp) * 2 + 1];
    }
    float m = s / n;
    mean[c] = m;
    istd[c] = rsqrtf(sq / n - m * m + 1e-5f);
}

// ---------------- BN + ReLU + 3x3/2 maxpool fused ----------------
__global__ void bn_relu_pool(
    const float* __restrict__ x, const float* __restrict__ mean, const float* __restrict__ istd,
    float* __restrict__ out, int B, int C, int H, int W, int Ho, int Wo)
{
    int idx = blockIdx.x * blockDim.x + threadIdx.x;
    int total = B * C * Ho * Wo;
    if (idx >= total) return;
    int wo = idx % Wo; int t = idx / Wo;
    int ho = t % Ho;   t /= Ho;
    int c  = t % C;    int b = t / C;
    const float* xp = x + ((size_t)b * C + c) * H * W;
    float mx = -1e30f;
#pragma unroll
    for (int dy = 0; dy < 3; dy++)
#pragma unroll
        for (int dx = 0; dx < 3; dx++)
            mx = fmaxf(mx, xp[(2*ho + dy) * W + (2*wo + dx)]);
    float v = (mx - mean[c]) * istd[c];
    out[idx] = fmaxf(v, 0.f);
}

// ---------------- feature norms ----------------
__global__ __launch_bounds__(256) void feat_norms(
    const float* __restrict__ pool1, float* __restrict__ invn, int B, int C, int HW)
{
    int b = blockIdx.x;
    for (int n = threadIdx.x; n < HW; n += blockDim.x) {
        float s = 0.f;
        for (int c = 0; c < C; c++) {
            float v = pool1[((size_t)b * C + c) * HW + n];
            s += v * v;
        }
        invn[b * HW + n] = 1.f / fmaxf(sqrtf(s), 1e-12f);
    }
}

__global__ void feat_transpose(
    const float* __restrict__ pool1, const float* __restrict__ invn, float* __restrict__ featN,
    int B, int C, int HW)
{
    __shared__ float tile[32][33];
    int b = blockIdx.z;
    int n0 = blockIdx.x * 32, c0 = blockIdx.y * 32;
    for (int i = threadIdx.y; i < 32; i += 8) {
        int c = c0 + i, n = n0 + threadIdx.x;
        tile[i][threadIdx.x] = (c < C && n < HW) ? pool1[((size_t)b * C + c) * HW + n] : 0.f;
    }
    __syncthreads();
    for (int i = threadIdx.y; i < 32; i += 8) {
        int n = n0 + i, c = c0 + threadIdx.x;
        if (n < HW && c < C)
            featN[((size_t)b * HW + n) * C + c] = tile[threadIdx.x][i] * invn[b * HW + n];
    }
}

// ---------------- 128x128x8 register-blocked SGEMM NT with exp epilogue ----
__global__ __launch_bounds__(256) void sgemm128_exp(
    const float* __restrict__ A, const float* __restrict__ Bm, float* __restrict__ C,
    int M, int N, int K)
{
    __shared__ float As[8][128];
    __shared__ float Bs[8][128];
    int m0 = blockIdx.y * 128, n0 = blockIdx.x * 128;
    int tid = threadIdx.x;
    int tx = tid & 15, ty = tid >> 4;
    float acc[8][8];
#pragma unroll
    for (int i = 0; i < 8; i++)
#pragma unroll
        for (int j = 0; j < 8; j++) acc[i][j] = 0.f;

    int lr = tid >> 1, lk = (tid & 1) * 4;
    for (int k0 = 0; k0 < K; k0 += 8) {
        float4 va = *(const float4*)&A[(size_t)(m0 + lr) * K + k0 + lk];
        float4 vb = make_float4(0.f, 0.f, 0.f, 0.f);
        if (n0 + lr < N) vb = *(const float4*)&Bm[(size_t)(n0 + lr) * K + k0 + lk];
        As[lk+0][lr] = va.x; As[lk+1][lr] = va.y; As[lk+2][lr] = va.z; As[lk+3][lr] = va.w;
        Bs[lk+0][lr] = vb.x; Bs[lk+1][lr] = vb.y; Bs[lk+2][lr] = vb.z; Bs[lk+3][lr] = vb.w;
        __syncthreads();
#pragma unroll
        for (int kk = 0; kk < 8; kk++) {
            float a[8], b[8];
            *(float4*)&a[0] = *(const float4*)&As[kk][ty*8];
            *(float4*)&a[4] = *(const float4*)&As[kk][ty*8+4];
            *(float4*)&b[0] = *(const float4*)&Bs[kk][tx*8];
            *(float4*)&b[4] = *(const float4*)&Bs[kk][tx*8+4];
#pragma unroll
            for (int i = 0; i < 8; i++)
#pragma unroll
                for (int j = 0; j < 8; j++) acc[i][j] += a[i] * b[j];
        }
        __syncthreads();
    }
#pragma unroll
    for (int i = 0; i < 8; i++) {
        int r = m0 + ty*8 + i;
#pragma unroll
        for (int j = 0; j < 8; j++) {
            int cn = n0 + tx*8 + j;
            if (cn < N)
                C[(size_t)r * N + cn] = __expf(10.f * (acc[i][j] - 1.f));
        }
    }
}

// ---------------- SGEMM NT (fc layers) ----------------
__global__ __launch_bounds__(256) void sgemm_nt(
    const float* __restrict__ A, const float* __restrict__ Bm, float* __restrict__ C,
    int M, int N, int K, int epi, const float* __restrict__ bias)
{
    const int BK = 16;
    __shared__ float As[BK][64];
    __shared__ float Bs[BK][64];
    int m0 = blockIdx.y * 64, n0 = blockIdx.x * 64;
    int tid = threadIdx.x;
    int tx = tid % 16, ty = tid / 16;
    float acc[4][4];
#pragma unroll
    for (int i = 0; i < 4; i++)
#pragma unroll
        for (int j = 0; j < 4; j++) acc[i][j] = 0.f;

    int lr = tid / 4, lk = (tid % 4) * 4;
    for (int k0 = 0; k0 < K; k0 += BK) {
        float4 va = make_float4(0.f, 0.f, 0.f, 0.f);
        float4 vb = make_float4(0.f, 0.f, 0.f, 0.f);
        int gm = m0 + lr, gn = n0 + lr;
        if (gm < M) va = *(const float4*)&A[(size_t)gm * K + k0 + lk];
        if (gn < N) vb = *(const float4*)&Bm[(size_t)gn * K + k0 + lk];
        As[lk+0][lr] = va.x; As[lk+1][lr] = va.y; As[lk+2][lr] = va.z; As[lk+3][lr] = va.w;
        Bs[lk+0][lr] = vb.x; Bs[lk+1][lr] = vb.y; Bs[lk+2][lr] = vb.z; Bs[lk+3][lr] = vb.w;
        __syncthreads();
#pragma unroll
        for (int kk = 0; kk < BK; kk++) {
            float a[4], b[4];
#pragma unroll
            for (int i = 0; i < 4; i++) a[i] = As[kk][ty*4 + i];
#pragma unroll
            for (int j = 0; j < 4; j++) b[j] = Bs[kk][tx*4 + j];
#pragma unroll
            for (int i = 0; i < 4; i++)
#pragma unroll
                for (int j = 0; j < 4; j++) acc[i][j] += a[i] * b[j];
        }
        __syncthreads();
    }
#pragma unroll
    for (int i = 0; i < 4; i++) {
        int r = m0 + ty*4 + i;
        if (r >= M) continue;
#pragma unroll
        for (int j = 0; j < 4; j++) {
            int cn = n0 + tx*4 + j;
            if (cn >= N) continue;
            float v = acc[i][j];
            if (epi == 1) v = __expf(10.f * (v - 1.f));
            else if (epi == 2) v += bias[cn];
            C[(size_t)r * N + cn] = v;
        }
    }
}

__global__ void fill_kernel(float* p, float v, int n) {
    int i = blockIdx.x * blockDim.x + threadIdx.x;
    if (i < n) p[i] = v;
}

// ---------------- Sinkhorn ----------------
__global__ __launch_bounds__(320) void sink_colsum(
    const float* __restrict__ K, const float* __restrict__ u, float* __restrict__ part,
    int n1, int n2)
{
    int b = blockIdx.x, sp = blockIdx.y;
    int j = threadIdx.x;
    if (j >= n2) return;
    int chunk = (n1 + ISPLIT - 1) / ISPLIT;
    int i0 = sp * chunk;
    int i1 = min(n1, i0 + chunk);
    const float* Kb = K + (size_t)b * n1 * n2;
    const float* ub = u + (size_t)b * n1;
    float s = 0.f;
    int i = i0;
    for (; i + 4 <= i1; i += 4) {
        float k0 = Kb[(size_t)(i+0) * n2 + j];
        float k1 = Kb[(size_t)(i+1) * n2 + j];
        float k2 = Kb[(size_t)(i+2) * n2 + j];
        float k3 = Kb[(size_t)(i+3) * n2 + j];
        s += k0 * ub[i+0] + k1 * ub[i+1] + k2 * ub[i+2] + k3 * ub[i+3];
    }
    for (; i < i1; i++) s += Kb[(size_t)i * n2 + j] * ub[i];
    part[((size_t)b * ISPLIT + sp) * n2 + j] = s;
}

__global__ __launch_bounds__(320) void sink_vupdate(
    const float* __restrict__ part, float* __restrict__ v, int n2, float bmarg)
{
    int b = blockIdx.x, j = threadIdx.x;
    if (j >= n2) return;
    float s = 0.f;
#pragma unroll
    for (int sp = 0; sp < ISPLIT; sp++) s += part[((size_t)b * ISPLIT + sp) * n2 + j];
    v[b * n2 + j] = bmarg / s;
}

// Fused iteration: u_i = amarg/(K[i,:]·v) AND next colsum partials,
// with column partials accumulated in REGISTERS per lane (no per-row
// atomics); one warp-level atomic merge of 10 values at the end.
__global__ __launch_bounds__(256) void sink_fused(
    const float* __restrict__ K, const float* __restrict__ v, float* __restrict__ u,
    float* __restrict__ part, int n1, int n2, float amarg, int doPart)
{
    __shared__ float sv[320];
    __shared__ float spart[320];
    int b = blockIdx.y, sp = blockIdx.x;
    int tid = threadIdx.x;
    for (int j = tid; j < 320; j += 256) {
        sv[j] = (j < n2) ? v[b * n2 + j] : 0.f;
        spart[j] = 0.f;
    }
    __syncthreads();
    int chunk = (n1 + ISPLIT - 1) / ISPLIT;
    int i0 = sp * chunk, i1 = min(n1, i0 + chunk);
    int wid = tid >> 5, lane = tid & 31;
    float svr[10], colacc[10];
#pragma unroll
    for (int t = 0; t < 10; t++) {
        svr[t] = sv[lane + 32 * t];
        colacc[t] = 0.f;
    }
    for (int i = i0 + wid; i < i1; i += 8) {
        const float* Kr = K + ((size_t)b * n1 + i) * n2;
        float kreg[10];
        float s = 0.f;
#pragma unroll
        for (int t = 0; t < 10; t++) {
            int j = lane + 32 * t;
            float kv = (j < n2) ? Kr[j] : 0.f;
            kreg[t] = kv;
            s += kv * svr[t];
        }
#pragma unroll
        for (int o = 16; o > 0; o >>= 1) s += __shfl_xor_sync(0xFFFFFFFFu, s, o);
        float ui = amarg / s;          // all lanes hold ui after butterfly
        if (lane == 0) u[b * n1 + i] = ui;
#pragma unroll
        for (int t = 0; t < 10; t++) colacc[t] += kreg[t] * ui;
    }
    if (doPart) {
#pragma unroll
        for (int t = 0; t < 10; t++)
            atomicAdd(&spart[lane + 32 * t], colacc[t]);
        __syncthreads();
        for (int j = tid; j < n2; j += 256)
            part[((size_t)b * ISPLIT + sp) * n2 + j] = spart[j];
    }
}

// ---------------- z GEMM ----------------
__global__ __launch_bounds__(256) void z_gemm(
    const float* __restrict__ Km, const float* __restrict__ u, const float* __restrict__ v,
    const float* __restrict__ P, float* __restrict__ z, float Bscale)
{
    __shared__ float As[8][128];
    __shared__ float Bs[8][96];
    __shared__ float sv[304];
    int b = blockIdx.y;
    int i0 = blockIdx.x * 128;
    int tid = threadIdx.x;
    for (int j = tid; j < 304; j += 256) sv[j] = (j < NPROTO) ? v[b * NPROTO + j] : 0.f;
    __syncthreads();
    int tx = tid & 15, ty = tid >> 4;
    float acc[8][6];
#pragma unroll
    for (int i = 0; i < 8; i++)
#pragma unroll
        for (int c = 0; c < 6; c++) acc[i][c] = 0.f;

    const float* Kb = Km + (size_t)b * NPIX * NPROTO;
    int li = tid >> 1, lk = (tid & 1) * 4;
    for (int k0 = 0; k0 < NPROTO; k0 += 8) {
        float4 va = make_float4(0.f, 0.f, 0.f, 0.f);
        if (i0 + li < NPIX && k0 + lk < NPROTO)
            va = *(const float4*)&Kb[(size_t)(i0 + li) * NPROTO + k0 + lk];
        As[lk+0][li] = va.x * sv[k0+lk+0];
        As[lk+1][li] = va.y * sv[k0+lk+1];
        As[lk+2][li] = va.z * sv[k0+lk+2];
        As[lk+3][li] = va.w * sv[k0+lk+3];
        for (int idx = tid; idx < 768; idx += 256) {
            int kk = idx / 96, c = idx - kk * 96;
            Bs[kk][c] = (k0 + kk < NPROTO) ? __ldg(&P[(k0 + kk) * 96 + c]) : 0.f;
        }
        __syncthreads();
#pragma unroll
        for (int kk = 0; kk < 8; kk++) {
            float a[8], bb[6];
            *(float4*)&a[0] = *(const float4*)&As[kk][ty*8];
            *(float4*)&a[4] = *(const float4*)&As[kk][ty*8+4];
            *(float2*)&bb[0] = *(const float2*)&Bs[kk][tx*6];
            *(float2*)&bb[2] = *(const float2*)&Bs[kk][tx*6+2];
            *(float2*)&bb[4] = *(const float2*)&Bs[kk][tx*6+4];
#pragma unroll
            for (int i = 0; i < 8; i++)
#pragma unroll
                for (int c = 0; c < 6; c++) acc[i][c] += a[i] * bb[c];
        }
        __syncthreads();
    }
#pragma unroll
    for (int ii = 0; ii < 8; ii++) {
        int i = i0 + ty * 8 + ii;
        if (i >= NPIX) continue;
        float s = Bscale * __ldg(&u[b * NPIX + i]);
#pragma unroll
        for (int cc = 0; cc < 6; cc++)
            z[((size_t)b * 96 + tx * 6 + cc) * NPIX + i] = acc[ii][cc] * s;
    }
}

// ---------------- BN1d ----------------
__global__ void bn1d_stats(const float* __restrict__ x, float* __restrict__ mean,
                           float* __restrict__ istd, int B, int F)
{
    int f = blockIdx.x * blockDim.x + threadIdx.x;
    if (f >= F) return;
    float s = 0.f, sq = 0.f;
    for (int b = 0; b < B; b++) {
        float v = x[(size_t)b * F + f];
        s += v; sq += v * v;
    }
    float m = s / B;
    mean[f] = m;
    istd[f] = rsqrtf(sq / B - m * m + 1e-5f);
}

__global__ void bn1d_apply_relu(float* __restrict__ x, const float* __restrict__ mean,
                                const float* __restrict__ istd, int total, int F)
{
    int i = blockIdx.x * blockDim.x + threadIdx.x;
    if (i >= total) return;
    int f = i % F;
    float v = (x[i] - mean[f]) * istd[f];
    x[i] = fmaxf(v, 0.f);
}

__global__ __launch_bounds__(128) void l2norm_rows(
    const float* __restrict__ x, float* __restrict__ out, int N)
{
    int r = blockIdx.x, t = threadIdx.x;
    float v = x[r * N + t];
    float s = v * v;
#pragma unroll
    for (int o = 16; o > 0; o >>= 1) s += __shfl_xor_sync(0xFFFFFFFFu, s, o);
    __shared__ float ws[4];
    if ((t & 31) == 0) ws[t >> 5] = s;
    __syncthreads();
    float tot = ws[0] + ws[1] + ws[2] + ws[3];
    out[r * N + t] = v / sqrtf(tot);
}

// ---------------- host orchestration ----------------
static void run_bn2d(const float* x, float* p_part, float* p_mean, float* p_istd,
                     int C, int HW)
{
    bn2d_stats_part<<<dim3(C, BNSPLIT), 256>>>(x, p_part, BATCH, C, HW);
    bn2d_stats_fin<<<cdiv(C, 128), 128>>>(p_part, p_mean, p_istd, C, (float)BATCH * HW);
}

extern "C" void kernel_launch(void* const* d_in, const int* in_sizes, int n_in,
                              void* d_out, int out_size)
{
    const float* x      = (const float*)d_in[0];
    const float* sent_w = (const float*)d_in[1];
    const float* protos = (const float*)d_in[2];
    const float* w1     = (const float*)d_in[3];
    const float* w2     = (const float*)d_in[4];
    const float* w3     = (const float*)d_in[5];
    const float* w4     = (const float*)d_in[6];
    const float* w5     = (const float*)d_in[7];
    const float* w6     = (const float*)d_in[8];
    const float* w7     = (const float*)d_in[9];
    const float* b7     = (const float*)d_in[10];
    float* out = (float*)d_out;

    float *p_conv1, *p_pool1, *p_invn, *p_featN, *p_K, *p_u, *p_v, *p_part, *p_z;
    float *p_c2, *p_p2, *p_t1, *p_t2, *p_p4, *p_f1, *p_f2, *p_f3, *p_mean, *p_istd, *p_bnpart;
    cudaGetSymbolAddress((void**)&p_conv1, g_conv1);
    cudaGetSymbolAddress((void**)&p_pool1, g_pool1);
    cudaGetSymbolAddress((void**)&p_invn,  g_invn);
    cudaGetSymbolAddress((void**)&p_featN, g_featN);
    cudaGetSymbolAddress((void**)&p_K,     g_K);
    cudaGetSymbolAddress((void**)&p_u,     g_u);
    cudaGetSymbolAddress((void**)&p_v,     g_v);
    cudaGetSymbolAddress((void**)&p_part,  g_part);
    cudaGetSymbolAddress((void**)&p_z,     g_z);
    cudaGetSymbolAddress((void**)&p_c2,    g_c2);
    cudaGetSymbolAddress((void**)&p_p2,    g_p2);
    cudaGetSymbolAddress((void**)&p_t1,    g_t1);
    cudaGetSymbolAddress((void**)&p_t2,    g_t2);
    cudaGetSymbolAddress((void**)&p_p4,    g_p4);
    cudaGetSymbolAddress((void**)&p_f1,    g_f1);
    cudaGetSymbolAddress((void**)&p_f2,    g_f2);
    cudaGetSymbolAddress((void**)&p_f3,    g_f3);
    cudaGetSymbolAddress((void**)&p_mean,  g_mean);
    cudaGetSymbolAddress((void**)&p_istd,  g_istd);
    cudaGetSymbolAddress((void**)&p_bnpart,g_bnpart);

    const int SM17 = (2 * 8 * (19 * 19) + 2 * 64 * 73) * 4;   // 60480 B
    const int SM35 = (2 * 8 * (11 * 37) + 2 * 64 * 73) * 4;   // 63424 B
    cudaFuncSetAttribute(conv_bf16<10>, cudaFuncAttributeMaxDynamicSharedMemorySize,
                         SM35 > SM17 ? SM35 : SM17);

    dim3 cb(16, 16);

    // --- sentinel block: conv(2->96, 72x72) + BN + ReLU + pool(72->35)
    {
        int tilesX = cdiv(H1, 16);
        dim3 grid(tilesX * tilesX, C1 / CT, BATCH);
        conv3x3<<<grid, cb>>>(x, sent_w, p_conv1, BATCH, 2, H1, H1, C1, tilesX);
        run_bn2d(p_conv1, p_bnpart, p_mean, p_istd, C1, H1 * H1);
        int total = BATCH * C1 * P1 * P1;
        bn_relu_pool<<<cdiv(total, 256), 256>>>(p_conv1, p_mean, p_istd, p_pool1,
                                                BATCH, C1, H1, H1, P1, P1);
    }

    // --- feature normalize + transpose
    feat_norms<<<BATCH, 256>>>(p_pool1, p_invn, BATCH, C1, NPIX);
    {
        dim3 grid(cdiv(NPIX, 32), cdiv(C1, 32), BATCH);
        feat_transpose<<<grid, dim3(32, 8)>>>(p_pool1, p_invn, p_featN, BATCH, C1, NPIX);
    }

    // --- S = featN @ protos^T, fused K = exp(10*(S-1))
    {
        dim3 grid(cdiv(NPROTO, 128), (BATCH * NPIX) / 128);
        sgemm128_exp<<<grid, 256>>>(p_featN, protos, p_K, BATCH * NPIX, NPROTO, C1);
    }

    // --- Sinkhorn: initial colsum (u=1), then 10 fused iterations (1 K pass each)
    fill_kernel<<<cdiv(BATCH * NPIX, 256), 256>>>(p_u, 1.f, BATCH * NPIX);
    const float amarg = 1.f / (float)NPIX;
    const float bmarg = 1.f / (float)NPROTO;
    sink_colsum<<<dim3(BATCH, ISPLIT), 320>>>(p_K, p_u, p_part, NPIX, NPROTO);
    for (int it = 0; it < 10; it++) {
        sink_vupdate<<<BATCH, 320>>>(p_part, p_v, NPROTO, bmarg);
        sink_fused<<<dim3(ISPLIT, BATCH), 256>>>(p_K, p_v, p_u, p_part,
                                                 NPIX, NPROTO, amarg, it < 9);
    }

    // --- z = B * diag(u) K diag(v) protos
    z_gemm<<<dim3(cdiv(NPIX, 128), BATCH), 256>>>(p_K, p_u, p_v, protos, p_z, (float)BATCH);

    // --- block: conv(96->192, 35x35) + BN + ReLU + pool(35->17); 4 bands of 9 rows
    {
        dim3 grid(4, C2 / 64, BATCH);
        conv_bf16<10><<<grid, 256, SM35>>>(p_z, w1, p_c2, C1, P1, P1, C2, 9, nullptr, nullptr);
        run_bn2d(p_c2, p_bnpart, p_mean, p_istd, C2, P1 * P1);
        int total = BATCH * C2 * P2 * P2;
        bn_relu_pool<<<cdiv(total, 256), 256>>>(p_c2, p_mean, p_istd, p_p2,
                                                BATCH, C2, P1, P1, P2, P2);
    }

    // --- block: conv(192->384, 17x17) -> t1 (raw); stats for t1
    {
        dim3 grid(1, C3 / 64, BATCH);
        conv_bf16<10><<<grid, 256, SM17>>>(p_p2, w2, p_t1, C2, P2, P2, C3, 17, nullptr, nullptr);
        run_bn2d(p_t1, p_bnpart, p_mean, p_istd, C3, P2 * P2);
    }

    // --- block: conv(384->384, 17x17), input BN+ReLU fused into staging -> t2 (raw)
    {
        dim3 grid(1, C3 / 64, BATCH);
        conv_bf16<10><<<grid, 256, SM17>>>(p_t1, w3, p_t2, C3, P2, P2, C3, 17, p_mean, p_istd);
        run_bn2d(p_t2, p_bnpart, p_mean, p_istd, C3, P2 * P2);
    }

    // --- block: conv(384->192, 17x17), input BN+ReLU fused -> t1 (raw), then BN+ReLU+pool
    {
        dim3 grid(1, C2 / 64, BATCH);
        conv_bf16<10><<<grid, 256, SM17>>>(p_t2, w4, p_t1, C3, P2, P2, C2, 17, p_mean, p_istd);
        run_bn2d(p_t1, p_bnpart, p_mean, p_istd, C2, P2 * P2);
        int total = BATCH * C2 * P4 * P4;
        bn_relu_pool<<<cdiv(total, 256), 256>>>(p_t1, p_mean, p_istd, p_p4,
                                                BATCH, C2, P2, P2, P4, P4);
    }

    // --- fc5
    {
        dim3 grid(cdiv(FDIM, 64), cdiv(BATCH, 64));
        sgemm_nt<<<grid, 256>>>(p_p4, w5, p_f1, BATCH, FDIM, F5IN, 0, nullptr);
        bn1d_stats<<<cdiv(FDIM, 256), 256>>>(p_f1, p_mean, p_istd, BATCH, FDIM);
        bn1d_apply_relu<<<cdiv(BATCH * FDIM, 256), 256>>>(p_f1, p_mean, p_istd, BATCH * FDIM, FDIM);
    }

    // --- fc6
    {
        dim3 grid(cdiv(FDIM, 64), cdiv(BATCH, 64));
        sgemm_nt<<<grid, 256>>>(p_f1, w6, p_f2, BATCH, FDIM, FDIM, 0, nullptr);
        bn1d_stats<<<cdiv(FDIM, 256), 256>>>(p_f2, p_mean, p_istd, BATCH, FDIM);
        bn1d_apply_relu<<<cdiv(BATCH * FDIM, 256), 256>>>(p_f2, p_mean, p_istd, BATCH * FDIM, FDIM);
    }

    // --- fc7 + L2 normalize
    {
        dim3 grid(cdiv(OUTD, 64), cdiv(BATCH, 64));
        sgemm_nt<<<grid, 256>>>(p_f2, w7, p_f3, BATCH, OUTD, FDIM, 2, b7);
        l2norm_rows<<<BATCH, 128>>>(p_f3, out, OUTD);
    }
}